// round 1
// baseline (speedup 1.0000x reference)
#include <cuda_runtime.h>
#include <cuda_bf16.h>
#include <cstdint>

// FreezedScaledFakeQuantize: out = (clip(round(X/s + zp), qmin, qmax) - zp) * s
// X: [8192, 8192] fp32, scale/zp: [8192, 64] fp32 (group size 128 along cols),
// qmin/qmax: int32 scalars. Output fp32, same shape as X.
//
// Memory-bound streaming kernel: 256 MB in + 256 MB out. One float4 per
// thread; all 4 lanes of a float4 share one (scale, zp) pair since
// GROUP_SIZE=128 is a multiple of 4. Division hoisted to one rcp per float4.

#define COLS_LOG2 13          // 8192 cols
#define F4_PER_ROW_LOG2 11    // 2048 float4 per row
#define F4_PER_GROUP_LOG2 5   // 32 float4 per 128-col group
#define N_GROUPS 64
#define N_GROUPS_LOG2 6

__global__ void __launch_bounds__(256) fq_kernel(
    const float4* __restrict__ X,
    const float*  __restrict__ scale,
    const float*  __restrict__ zero_point,
    const int*    __restrict__ qmin_p,
    const int*    __restrict__ qmax_p,
    float4*       __restrict__ out)
{
    const unsigned i = blockIdx.x * blockDim.x + threadIdx.x;  // float4 index

    // row = i >> 11; group = (i >> 5) & 63; sidx = row*64 + group
    const unsigned row  = i >> F4_PER_ROW_LOG2;
    const unsigned grp  = (i >> F4_PER_GROUP_LOG2) & (N_GROUPS - 1);
    const unsigned sidx = (row << N_GROUPS_LOG2) + grp;

    const float s   = __ldg(&scale[sidx]);
    const float zp  = __ldg(&zero_point[sidx]);
    const float inv = 1.0f / s;

    const float qmin = (float)__ldg(qmin_p);
    const float qmax = (float)__ldg(qmax_p);

    const float4 x = X[i];

    float4 r;
    r.x = (fminf(fmaxf(rintf(fmaf(x.x, inv, zp)), qmin), qmax) - zp) * s;
    r.y = (fminf(fmaxf(rintf(fmaf(x.y, inv, zp)), qmin), qmax) - zp) * s;
    r.z = (fminf(fmaxf(rintf(fmaf(x.z, inv, zp)), qmin), qmax) - zp) * s;
    r.w = (fminf(fmaxf(rintf(fmaf(x.w, inv, zp)), qmin), qmax) - zp) * s;

    out[i] = r;
}

extern "C" void kernel_launch(void* const* d_in, const int* in_sizes, int n_in,
                              void* d_out, int out_size)
{
    const float4* X   = (const float4*)d_in[0];
    const float*  sc  = (const float*)d_in[1];
    const float*  zp  = (const float*)d_in[2];
    const int*    qmn = (const int*)d_in[3];
    const int*    qmx = (const int*)d_in[4];
    float4*       out = (float4*)d_out;

    const int n_f4 = out_size / 4;                 // 16,777,216
    const int threads = 256;
    const int blocks = (n_f4 + threads - 1) / threads;  // 65,536

    fq_kernel<<<blocks, threads>>>(X, sc, zp, qmn, qmx, out);
}

// round 2
// speedup vs baseline: 1.2614x; 1.2614x over previous
#include <cuda_runtime.h>
#include <cuda_bf16.h>
#include <cstdint>

// FreezedScaledFakeQuantize: out = (clip(round(X/s + zp), qmin, qmax) - zp) * s
// X: [8192, 8192] fp32, scale/zp: [8192, 64] fp32 (group 128 cols), int32 qmin/qmax.
//
// Round 2: 4 front-batched independent LDG.128 per thread (MLP=4) in a
// block-strided layout, streaming cache hints on the 512 MB X/out stream.

#define F4_PER_ROW_LOG2 11    // 2048 float4 per row
#define F4_PER_GROUP_LOG2 5   // 32 float4 per 128-col group
#define N_GROUPS_LOG2 6       // 64 groups per row
#define UNROLL 4
#define TPB 256

__global__ void __launch_bounds__(TPB) fq_kernel(
    const float4* __restrict__ X,
    const float*  __restrict__ scale,
    const float*  __restrict__ zero_point,
    const int*    __restrict__ qmin_p,
    const int*    __restrict__ qmax_p,
    float4*       __restrict__ out)
{
    const unsigned base = blockIdx.x * (TPB * UNROLL) + threadIdx.x;

    const float qmin = (float)__ldg(qmin_p);
    const float qmax = (float)__ldg(qmax_p);

    unsigned idx[UNROLL];
    float4   x[UNROLL];
    float    s[UNROLL], zp[UNROLL];

    // Front-batch all global loads (independent -> deep MLP).
    #pragma unroll
    for (int k = 0; k < UNROLL; ++k) {
        idx[k] = base + k * TPB;
        x[k] = __ldcs(&X[idx[k]]);           // streaming: touched once
    }
    #pragma unroll
    for (int k = 0; k < UNROLL; ++k) {
        const unsigned row  = idx[k] >> F4_PER_ROW_LOG2;
        const unsigned grp  = (idx[k] >> F4_PER_GROUP_LOG2) & ((1u << N_GROUPS_LOG2) - 1u);
        const unsigned sidx = (row << N_GROUPS_LOG2) + grp;
        s[k]  = __ldg(&scale[sidx]);         // hot 2 MB, keep cached
        zp[k] = __ldg(&zero_point[sidx]);
    }

    #pragma unroll
    for (int k = 0; k < UNROLL; ++k) {
        const float inv = 1.0f / s[k];
        float4 r;
        r.x = (fminf(fmaxf(rintf(fmaf(x[k].x, inv, zp[k])), qmin), qmax) - zp[k]) * s[k];
        r.y = (fminf(fmaxf(rintf(fmaf(x[k].y, inv, zp[k])), qmin), qmax) - zp[k]) * s[k];
        r.z = (fminf(fmaxf(rintf(fmaf(x[k].z, inv, zp[k])), qmin), qmax) - zp[k]) * s[k];
        r.w = (fminf(fmaxf(rintf(fmaf(x[k].w, inv, zp[k])), qmin), qmax) - zp[k]) * s[k];
        __stcs(&out[idx[k]], r);             // streaming store
    }
}

extern "C" void kernel_launch(void* const* d_in, const int* in_sizes, int n_in,
                              void* d_out, int out_size)
{
    const float4* X   = (const float4*)d_in[0];
    const float*  sc  = (const float*)d_in[1];
    const float*  zp  = (const float*)d_in[2];
    const int*    qmn = (const int*)d_in[3];
    const int*    qmx = (const int*)d_in[4];
    float4*       out = (float4*)d_out;

    const int n_f4   = out_size / 4;                  // 16,777,216
    const int blocks = n_f4 / (TPB * UNROLL);         // 16,384

    fq_kernel<<<blocks, TPB>>>(X, sc, zp, qmn, qmx, out);
}